// round 6
// baseline (speedup 1.0000x reference)
#include <cuda_runtime.h>
#include <cstddef>

// Problem constants
#define TT 512
#define BB 256
#define FF 64
#define UU 128
#define NR 2              // batch rows per CTA
#define NCTA (BB / NR)    // 128 CTAs
#define NTHREADS 256

// Output layout: out_seq (T,B,5F) then hT (B,U) then tsT (B,F) then dtT (B,F)
#define OFF_H  ((size_t)TT * BB * 5 * FF)          // 41,943,040
#define OFF_TS (OFF_H + (size_t)BB * UU)           // +32768
#define OFF_DT (OFF_TS + (size_t)BB * FF)          // +16384

struct Smem {
    // persistent cached weights
    float u_upd[UU * UU];      // u_update  (128x128)
    float w_upd[2 * FF * UU];  // w_update  (128x128)
    float u_rst[UU * UU];      // u_reset   (128x128)
    float w_corrm[FF * FF];    // off-diag masked w_corr (64x64)
    float bctl[FF];
    float bcorr[FF];
    // per-row state / temporaries
    float h[NR][UU];
    float dh[NR][UU];
    float decay[NR][UU];
    float rg[NR][UU];
    float zbuf[NR][UU];
    float ts[NR][FF];
    float dtv[NR][FF];
    float xreg[NR][FF];
    float xcur[NR][FF];
    float mm[NR][FF];
    float zc[NR][FF];
    float cc[NR][FF];
    float xt[NR][5 * FF];
    float scratch[1024];
};

__global__ void __launch_bounds__(NTHREADS, 1)
padd_gru_kernel(const float* __restrict__ inputs,
                const float* __restrict__ h0,
                const float* __restrict__ ts0,
                const float* __restrict__ dt0,
                const float* __restrict__ w_regression,
                const float* __restrict__ b_regression,
                const float* __restrict__ w_controleur,
                const float* __restrict__ b_controleur,
                const float* __restrict__ w_delta,
                const float* __restrict__ b_delta,
                const float* __restrict__ w_value_mask,
                const float* __restrict__ b_value_mask,
                const float* __restrict__ w_corr,
                const float* __restrict__ b_corr,
                const float* __restrict__ w_concat,
                const float* __restrict__ b_concat,
                const float* __restrict__ u_update,
                const float* __restrict__ w_update,
                const float* __restrict__ b_update,
                const float* __restrict__ u_reset,
                const float* __restrict__ w_reset,
                const float* __restrict__ b_reset,
                float* __restrict__ out)
{
    extern __shared__ float smem_raw[];
    Smem& S = *reinterpret_cast<Smem*>(smem_raw);
    const int tid = threadIdx.x;
    const int b0 = blockIdx.x * NR;

    // ---- prologue: cache weights + init state ----
    for (int i = tid; i < UU * UU; i += NTHREADS) S.u_upd[i] = u_update[i];
    for (int i = tid; i < 2 * FF * UU; i += NTHREADS) S.w_upd[i] = w_update[i];
    for (int i = tid; i < UU * UU; i += NTHREADS) S.u_rst[i] = u_reset[i];
    for (int i = tid; i < FF * FF; i += NTHREADS) {
        int rr = i / FF, cc2 = i % FF;
        S.w_corrm[i] = (rr == cc2) ? 0.0f : w_corr[i];
    }
    for (int i = tid; i < FF; i += NTHREADS) { S.bctl[i] = b_controleur[i]; S.bcorr[i] = b_corr[i]; }
    {
        float* hp = &S.h[0][0];
        for (int i = tid; i < NR * UU; i += NTHREADS) hp[i] = h0[(size_t)b0 * UU + i];
        float* tp = &S.ts[0][0];
        float* dp = &S.dtv[0][0];
        for (int i = tid; i < NR * FF; i += NTHREADS) {
            tp[i] = ts0[(size_t)b0 * FF + i];
            dp[i] = dt0[(size_t)b0 * FF + i];
        }
    }
    const float breg = b_regression[0];
    const float bdel = b_delta[0];
    const float bvm  = b_value_mask[0];
    const float bcc  = b_concat[0];
    const float bupd = b_update[0];
    const float brst = b_reset[0];
    __syncthreads();

    for (int t = 0; t < TT; ++t) {
        // ---- S0: load x_t + stage A partials (x_reg, tv); streamed w_reg/w_ctl, unique loads ----
        {
            float* xtp = &S.xt[0][0];
            for (int i = tid; i < NR * 5 * FF; i += NTHREADS) {
                int r = i / (5 * FF), c = i % (5 * FF);
                xtp[i] = inputs[((size_t)(b0 + r) * TT + t) * (5 * FF) + c];
            }
        }
        {
            const int f = tid & 63;
            const int half = (tid >> 6) & 1;
            const int mat = tid >> 7;  // 0: regression, 1: controleur
            const float* W = mat ? w_controleur : w_regression;
            float a0 = 0.f, a1 = 0.f;
            const int u0 = half * 64;
#pragma unroll 8
            for (int u = u0; u < u0 + 64; ++u) {
                float w = W[u * FF + f];
                a0 += w * S.h[0][u];
                a1 += w * S.h[1][u];
            }
            S.scratch[((mat * 2 + half) * 2 + 0) * FF + f] = a0;
            S.scratch[((mat * 2 + half) * 2 + 1) * FF + f] = a1;
        }
        __syncthreads();

        // ---- S1: combine A + timestamp/mask elementwise; write x_reg, ti, dt outputs ----
        if (tid < NR * FF) {
            const int r = tid >> 6, f = tid & 63;
            float xr = S.scratch[(0 + r) * FF + f] + S.scratch[(2 + r) * FF + f] + breg;
            float tv = fabsf(S.scratch[(4 + r) * FF + f] + S.scratch[(6 + r) * FF + f] + S.bctl[f]);
            float ti_in = S.xt[r][f];
            float x_in  = S.xt[r][FF + f];
            float m     = S.xt[r][2 * FF + f];
            float dt_in = S.xt[r][3 * FF + f];
            float pad   = S.xt[r][4 * FF + f];
            float pts = S.ts[r][f], pdt = S.dtv[r][f];
            float cand = pts + tv;
            float ti = pad * ti_in + (1.f - pad) * cand;
            ti = (ti <= 100.0f) ? ti : pts;
            float dgen = (cand <= 100.0f) ? tv : pdt;
            float ndt = pad * dt_in + (1.f - pad) * dgen;
            float xc = m * x_in + (1.f - m) * xr;
            S.xreg[r][f] = xr;
            S.ts[r][f]   = ti;
            S.dtv[r][f]  = ndt;
            S.xcur[r][f] = xc;
            S.mm[r][f]   = m;
            size_t ob = ((size_t)t * BB + (b0 + r)) * (5 * FF);
            out[ob + f]          = xr;
            out[ob + 3 * FF + f] = ti;
            out[ob + 4 * FF + f] = ndt;
        }
        __syncthreads();

        // ---- S2: w_delta partials (streamed, unique) + z_corr (smem) ----
        {
            const int u = tid & 127;
            const int half = tid >> 7;
            float a0 = 0.f, a1 = 0.f;
            const int f0 = half * 32;
#pragma unroll 8
            for (int f = f0; f < f0 + 32; ++f) {
                float w = w_delta[f * UU + u];
                a0 += S.dtv[0][f] * w;
                a1 += S.dtv[1][f] * w;
            }
            S.scratch[(half * 2 + 0) * UU + u] = a0;
            S.scratch[(half * 2 + 1) * UU + u] = a1;
        }
        if (tid < NR * FF) {
            const int r = tid >> 6, f = tid & 63;
            float acc = S.bcorr[f];
#pragma unroll 8
            for (int k = 0; k < FF; ++k) acc += S.xcur[r][k] * S.w_corrm[k * FF + f];
            S.zc[r][f] = acc;
            out[((size_t)t * BB + (b0 + r)) * (5 * FF) + FF + f] = acc;
        }
        __syncthreads();

        // ---- S3: decay = exp(-relu(.)); dh = decay*h ----
        {
            const int r = tid >> 7, u = tid & 127;
            float d = S.scratch[(0 + r) * UU + u] + S.scratch[(2 + r) * UU + u] + bdel;
            float dec = expf(-fmaxf(d, 0.f));
            S.decay[r][u] = dec;
            S.dh[r][u] = dec * S.h[r][u];
        }
        __syncthreads();

        // ---- S4: beta partials: [m,decay] @ w_concat (K=192 split into 4x48, streamed unique) ----
        {
            const int f = tid & 63, q = tid >> 6;
            float a0 = 0.f, a1 = 0.f;
            const int k0 = q * 48;
#pragma unroll 8
            for (int k = k0; k < k0 + 48; ++k) {
                float w = w_concat[k * FF + f];
                float v0 = (k < FF) ? S.mm[0][k] : S.decay[0][k - FF];
                float v1 = (k < FF) ? S.mm[1][k] : S.decay[1][k - FF];
                a0 += w * v0;
                a1 += w * v1;
            }
            S.scratch[(q * 2 + 0) * FF + f] = a0;
            S.scratch[(q * 2 + 1) * FF + f] = a1;
        }
        __syncthreads();

        // ---- S5: beta combine, c_t, c; write c output ----
        if (tid < NR * FF) {
            const int r = tid >> 6, f = tid & 63;
            float s = S.scratch[(0 + r) * FF + f] + S.scratch[(2 + r) * FF + f]
                    + S.scratch[(4 + r) * FF + f] + S.scratch[(6 + r) * FF + f] + bcc;
            float beta = 1.f / (1.f + expf(-s));
            float zcv = S.zc[r][f];
            float xr  = S.xreg[r][f];
            float ct  = beta * zcv + (1.f - beta) * xr;
            float m   = S.mm[r][f];
            float c   = m * S.xcur[r][f] + (1.f - m) * ct;
            S.cc[r][f] = c;
            out[((size_t)t * BB + (b0 + r)) * (5 * FF) + 2 * FF + f] = c;
        }
        __syncthreads();

        // ---- S6: z/r gate partials. half0: dh@u_upd/u_rst (smem). half1: cm@w_upd(smem)/w_reset(streamed unique) ----
        {
            const int u = tid & 127;
            const int half = tid >> 7;
            float az0 = 0.f, az1 = 0.f, ar0 = 0.f, ar1 = 0.f;
            if (half == 0) {
#pragma unroll 4
                for (int k = 0; k < UU; ++k) {
                    float wz = S.u_upd[k * UU + u];
                    float wr = S.u_rst[k * UU + u];
                    float d0 = S.dh[0][k], d1 = S.dh[1][k];
                    az0 += wz * d0; az1 += wz * d1;
                    ar0 += wr * d0; ar1 += wr * d1;
                }
            } else {
#pragma unroll 4
                for (int k = 0; k < FF; ++k) {
                    float wz = S.w_upd[k * UU + u];
                    float wr = w_reset[k * UU + u];
                    float c0 = S.cc[0][k], c1 = S.cc[1][k];
                    az0 += wz * c0; az1 += wz * c1;
                    ar0 += wr * c0; ar1 += wr * c1;
                }
#pragma unroll 4
                for (int k = 0; k < FF; ++k) {
                    float wz = S.w_upd[(FF + k) * UU + u];
                    float wr = w_reset[(FF + k) * UU + u];
                    float m0 = S.mm[0][k], m1 = S.mm[1][k];
                    az0 += wz * m0; az1 += wz * m1;
                    ar0 += wr * m0; ar1 += wr * m1;
                }
            }
            // layout: ((half*2+gate)*2+r)*UU+u
            S.scratch[((half * 2 + 0) * 2 + 0) * UU + u] = az0;
            S.scratch[((half * 2 + 0) * 2 + 1) * UU + u] = az1;
            S.scratch[((half * 2 + 1) * 2 + 0) * UU + u] = ar0;
            S.scratch[((half * 2 + 1) * 2 + 1) * UU + u] = ar1;
        }
        __syncthreads();

        // ---- S7: z, r; rg = r*dh ----
        {
            const int r = tid >> 7, u = tid & 127;
            float az = S.scratch[(0 + r) * UU + u] + S.scratch[(4 + r) * UU + u] + bupd;
            float ar = S.scratch[(2 + r) * UU + u] + S.scratch[(6 + r) * UU + u] + brst;
            float z  = 1.f / (1.f + expf(-az));
            float rr = 1.f / (1.f + expf(-ar));
            S.zbuf[r][u] = z;
            S.rg[r][u] = rr * S.dh[r][u];
        }
        __syncthreads();

        // ---- S8: h_hat partials. half0: rg@u_upd (smem). half1: cm@w_value_mask (streamed unique) ----
        {
            const int u = tid & 127;
            const int half = tid >> 7;
            float a0 = 0.f, a1 = 0.f;
            if (half == 0) {
#pragma unroll 4
                for (int k = 0; k < UU; ++k) {
                    float w = S.u_upd[k * UU + u];
                    a0 += w * S.rg[0][k];
                    a1 += w * S.rg[1][k];
                }
            } else {
#pragma unroll 4
                for (int k = 0; k < FF; ++k) {
                    float w = w_value_mask[k * UU + u];
                    a0 += w * S.cc[0][k];
                    a1 += w * S.cc[1][k];
                }
#pragma unroll 4
                for (int k = 0; k < FF; ++k) {
                    float w = w_value_mask[(FF + k) * UU + u];
                    a0 += w * S.mm[0][k];
                    a1 += w * S.mm[1][k];
                }
            }
            S.scratch[(half * 2 + 0) * UU + u] = a0;
            S.scratch[(half * 2 + 1) * UU + u] = a1;
        }
        __syncthreads();

        // ---- S9: h_hat combine + h update ----
        {
            const int r = tid >> 7, u = tid & 127;
            float s = S.scratch[(0 + r) * UU + u] + S.scratch[(2 + r) * UU + u] + bvm;
            float hh = tanhf(s);
            float z = S.zbuf[r][u];
            S.h[r][u] = (1.f - z) * S.h[r][u] + z * hh;
        }
        __syncthreads();
    }

    // ---- epilogue: final carries ----
    {
        const int r = tid >> 7, u = tid & 127;
        out[OFF_H + (size_t)(b0 + r) * UU + u] = S.h[r][u];
    }
    if (tid < NR * FF) {
        const int r = tid >> 6, f = tid & 63;
        out[OFF_TS + (size_t)(b0 + r) * FF + f] = S.ts[r][f];
        out[OFF_DT + (size_t)(b0 + r) * FF + f] = S.dtv[r][f];
    }
}

extern "C" void kernel_launch(void* const* d_in, const int* in_sizes, int n_in,
                              void* d_out, int out_size) {
    const float* inputs        = (const float*)d_in[0];
    const float* h0            = (const float*)d_in[1];
    const float* ts0           = (const float*)d_in[2];
    const float* dt0           = (const float*)d_in[3];
    const float* w_regression  = (const float*)d_in[4];
    const float* b_regression  = (const float*)d_in[5];
    const float* w_controleur  = (const float*)d_in[6];
    const float* b_controleur  = (const float*)d_in[7];
    const float* w_delta       = (const float*)d_in[8];
    const float* b_delta       = (const float*)d_in[9];
    const float* w_value_mask  = (const float*)d_in[10];
    const float* b_value_mask  = (const float*)d_in[11];
    const float* w_corr        = (const float*)d_in[12];
    const float* b_corr        = (const float*)d_in[13];
    const float* w_concat      = (const float*)d_in[14];
    const float* b_concat      = (const float*)d_in[15];
    const float* u_update      = (const float*)d_in[16];
    const float* w_update      = (const float*)d_in[17];
    const float* b_update      = (const float*)d_in[18];
    const float* u_reset       = (const float*)d_in[19];
    const float* w_reset       = (const float*)d_in[20];
    const float* b_reset       = (const float*)d_in[21];
    float* out = (float*)d_out;

    cudaFuncSetAttribute(padd_gru_kernel,
                         cudaFuncAttributeMaxDynamicSharedMemorySize,
                         (int)sizeof(Smem));
    padd_gru_kernel<<<NCTA, NTHREADS, sizeof(Smem)>>>(
        inputs, h0, ts0, dt0,
        w_regression, b_regression, w_controleur, b_controleur,
        w_delta, b_delta, w_value_mask, b_value_mask,
        w_corr, b_corr, w_concat, b_concat,
        u_update, w_update, b_update,
        u_reset, w_reset, b_reset,
        out);
}

// round 8
// speedup vs baseline: 2.4023x; 2.4023x over previous
#include <cuda_runtime.h>
#include <cstddef>

// Problem constants
#define TT 512
#define BB 256
#define FF 64
#define UU 128
#define NR 2              // batch rows per CTA
#define NCTA (BB / NR)    // 128 CTAs
#define NTHREADS 512

// Output layout: out_seq (T,B,5F) then hT (B,U) then tsT (B,F) then dtT (B,F)
#define OFF_H  ((size_t)TT * BB * 5 * FF)
#define OFF_TS (OFF_H + (size_t)BB * UU)
#define OFF_DT (OFF_TS + (size_t)BB * FF)

struct Smem {
    // persistent cached gate weights (fp32)
    float u_upd[UU * UU];     // u_update  128x128
    float w_upd[UU * UU];     // w_update  (2F x U) 128x128
    float u_rst[UU * UU];     // u_reset   128x128
    float bctl[FF];
    float bcorr[FF];
    // row-interleaved state: [dim] -> {row0, row1}
    float2 h2[UU];
    float2 dh2[UU];
    float2 decay2[UU];
    float2 rg2[UU];
    float2 zbuf2[UU];
    float2 ts2[FF];
    float2 dtv2[FF];
    float2 xreg2[FF];
    float2 xcur2[FF];
    float2 mm2[FF];
    float2 zc2[FF];
    float2 cm2[2 * FF];       // [c(64) | m(64)] interleaved rows
    float xbuf[2][NR][5 * FF]; // double-buffered inputs (prefetch t+1)
    float scratch[3072];       // partial sums
};

__device__ __forceinline__ float sigmoidf_(float x) {
    return 1.0f / (1.0f + expf(-x));
}

__global__ void __launch_bounds__(NTHREADS, 1)
padd_gru_kernel(const float* __restrict__ inputs,
                const float* __restrict__ h0,
                const float* __restrict__ ts0,
                const float* __restrict__ dt0,
                const float* __restrict__ w_regression,
                const float* __restrict__ b_regression,
                const float* __restrict__ w_controleur,
                const float* __restrict__ b_controleur,
                const float* __restrict__ w_delta,
                const float* __restrict__ b_delta,
                const float* __restrict__ w_value_mask,
                const float* __restrict__ b_value_mask,
                const float* __restrict__ w_corr,
                const float* __restrict__ b_corr,
                const float* __restrict__ w_concat,
                const float* __restrict__ b_concat,
                const float* __restrict__ u_update,
                const float* __restrict__ w_update,
                const float* __restrict__ b_update,
                const float* __restrict__ u_reset,
                const float* __restrict__ w_reset,
                const float* __restrict__ b_reset,
                float* __restrict__ out)
{
    extern __shared__ float smem_raw[];
    Smem& S = *reinterpret_cast<Smem*>(smem_raw);
    const int tid = threadIdx.x;
    const int b0 = blockIdx.x * NR;

    // ---- common index helpers ----
    const int fp = tid & 31;          // f-pair index (32 pairs cover F=64)
    const int f0 = fp * 2;
    const int up = tid & 63;          // u-pair index (64 pairs cover U=128)
    const int u0 = up * 2;

    // ---- prologue: cache gate weights in smem ----
    for (int i = tid; i < UU * UU; i += NTHREADS) S.u_upd[i] = u_update[i];
    for (int i = tid; i < UU * UU; i += NTHREADS) S.w_upd[i] = w_update[i];
    for (int i = tid; i < UU * UU; i += NTHREADS) S.u_rst[i] = u_reset[i];
    for (int i = tid; i < FF; i += NTHREADS) { S.bctl[i] = b_controleur[i]; S.bcorr[i] = b_corr[i]; }

    // ---- state init (row-interleaved) ----
    if (tid < UU) {
        S.h2[tid] = make_float2(h0[(size_t)b0 * UU + tid], h0[(size_t)(b0 + 1) * UU + tid]);
    } else if (tid < UU + FF) {
        int f = tid - UU;
        S.ts2[f]  = make_float2(ts0[(size_t)b0 * FF + f], ts0[(size_t)(b0 + 1) * FF + f]);
        S.dtv2[f] = make_float2(dt0[(size_t)b0 * FF + f], dt0[(size_t)(b0 + 1) * FF + f]);
    }
    // prefetch x for t=0
    if (tid < 320) {
        int r = tid / 160, c2 = tid - r * 160;
        const float2* src = reinterpret_cast<const float2*>(inputs + ((size_t)(b0 + r) * TT) * (5 * FF));
        reinterpret_cast<float2*>(&S.xbuf[0][r][0])[c2] = src[c2];
    }

    // ---- loop-invariant weight slices in registers ----
    // S0: x_reg / tv matvec. group g16 in [0,16): mat = g16>>3, K-eighth = (g16&7)*16
    const int g16 = tid >> 5;
    const int s0_k0 = (g16 & 7) * 16;
    float2 wv[16];
    {
        const float* W = (g16 >> 3) ? w_controleur : w_regression;
#pragma unroll
        for (int i = 0; i < 16; ++i)
            wv[i] = *reinterpret_cast<const float2*>(W + (size_t)(s0_k0 + i) * FF + f0);
    }
    // S2: w_delta matvec for tid<256: K-quarter (tid>>6)&3, 16 rows each
    float2 wd[16];
    if (tid < 256) {
        const int k0 = ((tid >> 6) & 3) * 16;
#pragma unroll
        for (int i = 0; i < 16; ++i)
            wd[i] = *reinterpret_cast<const float2*>(w_delta + (size_t)(k0 + i) * UU + u0);
    }

    const float breg = b_regression[0];
    const float bdel = b_delta[0];
    const float bvm  = b_value_mask[0];
    const float bcc  = b_concat[0];
    const float bupd = b_update[0];
    const float brst = b_reset[0];
    __syncthreads();

    float* const ts_s   = reinterpret_cast<float*>(S.ts2);
    float* const dtv_s  = reinterpret_cast<float*>(S.dtv2);
    float* const xreg_s = reinterpret_cast<float*>(S.xreg2);
    float* const xcur_s = reinterpret_cast<float*>(S.xcur2);
    float* const mm_s   = reinterpret_cast<float*>(S.mm2);
    float* const zc_s   = reinterpret_cast<float*>(S.zc2);
    float* const cm_s   = reinterpret_cast<float*>(S.cm2);
    float* const dec_s  = reinterpret_cast<float*>(S.decay2);
    float* const dh_s   = reinterpret_cast<float*>(S.dh2);
    float* const rg_s   = reinterpret_cast<float*>(S.rg2);
    float* const zb_s   = reinterpret_cast<float*>(S.zbuf2);
    float* const h_s    = reinterpret_cast<float*>(S.h2);

    for (int t = 0; t < TT; ++t) {
        // ================= S0: x_reg / tv partials (reg-cached weights) + x prefetch =================
        {
            float a00 = 0.f, a01 = 0.f, a10 = 0.f, a11 = 0.f;
#pragma unroll
            for (int i = 0; i < 16; ++i) {
                float2 hk = S.h2[s0_k0 + i];
                float2 w = wv[i];
                a00 += w.x * hk.x; a01 += w.x * hk.y;
                a10 += w.y * hk.x; a11 += w.y * hk.y;
            }
            *reinterpret_cast<float4*>(&S.scratch[(g16 * FF + f0) * 2]) =
                make_float4(a00, a01, a10, a11);

            if (t + 1 < TT && tid < 320) {
                int r = tid / 160, c2 = tid - r * 160;
                const float2* src = reinterpret_cast<const float2*>(
                    inputs + ((size_t)(b0 + r) * TT + (t + 1)) * (5 * FF));
                reinterpret_cast<float2*>(&S.xbuf[(t + 1) & 1][r][0])[c2] = src[c2];
            }
        }
        __syncthreads();

        // ================= S1: combine + timestamp/mask elementwise =================
        if (tid < 128) {
            const int r = tid >> 6, f = tid & 63;
            float xr = breg, tvs = S.bctl[f];
#pragma unroll
            for (int kq = 0; kq < 8; ++kq) {
                xr  += S.scratch[(kq * FF + f) * 2 + r];
                tvs += S.scratch[((8 + kq) * FF + f) * 2 + r];
            }
            float tv = fabsf(tvs);
            const float* xb = S.xbuf[t & 1][r];
            float ti_in = xb[f];
            float x_in  = xb[FF + f];
            float m     = xb[2 * FF + f];
            float dt_in = xb[3 * FF + f];
            float pad   = xb[4 * FF + f];
            float pts = ts_s[f * 2 + r], pdt = dtv_s[f * 2 + r];
            float cand = pts + tv;
            float ti = pad * ti_in + (1.f - pad) * cand;
            ti = (ti <= 100.0f) ? ti : pts;
            float dgen = (cand <= 100.0f) ? tv : pdt;
            float ndt = pad * dt_in + (1.f - pad) * dgen;
            float xc = m * x_in + (1.f - m) * xr;
            ts_s[f * 2 + r]   = ti;
            dtv_s[f * 2 + r]  = ndt;
            xreg_s[f * 2 + r] = xr;
            xcur_s[f * 2 + r] = xc;
            mm_s[f * 2 + r]   = m;
            cm_s[(FF + f) * 2 + r] = m;   // cm = [c | m]; m half
            size_t ob = ((size_t)t * BB + (b0 + r)) * (5 * FF);
            out[ob + f]          = xr;
            out[ob + 3 * FF + f] = ti;
            out[ob + 4 * FF + f] = ndt;
        }
        __syncthreads();

        // ================= S2: w_delta partials (reg weights) || z_corr partials (streamed w_corr) =================
        if (tid < 256) {
            const int q = (tid >> 6) & 3;
            float a00 = 0.f, a01 = 0.f, a10 = 0.f, a11 = 0.f;
#pragma unroll
            for (int i = 0; i < 16; ++i) {
                float2 dk = S.dtv2[q * 16 + i];
                float2 w = wd[i];
                a00 += w.x * dk.x; a01 += w.x * dk.y;
                a10 += w.y * dk.x; a11 += w.y * dk.y;
            }
            *reinterpret_cast<float4*>(&S.scratch[(q * UU + u0) * 2]) =
                make_float4(a00, a01, a10, a11);
        } else {
            const int q8 = (tid >> 5) & 7;
            const int k0 = q8 * 8;
            float a00 = 0.f, a01 = 0.f, a10 = 0.f, a11 = 0.f;
#pragma unroll
            for (int i = 0; i < 8; ++i) {
                int k = k0 + i;
                float2 w = *reinterpret_cast<const float2*>(w_corr + (size_t)k * FF + f0);
                if (k == f0)     w.x = 0.f;   // off-diagonal mask
                if (k == f0 + 1) w.y = 0.f;
                float2 xk = S.xcur2[k];
                a00 += w.x * xk.x; a01 += w.x * xk.y;
                a10 += w.y * xk.x; a11 += w.y * xk.y;
            }
            *reinterpret_cast<float4*>(&S.scratch[2048 + (q8 * FF + f0) * 2]) =
                make_float4(a00, a01, a10, a11);
        }
        __syncthreads();

        // ================= S3: decay & dh || z_corr combine =================
        if (tid < 256) {
            const int r = tid >> 7, u = tid & 127;
            float d = bdel;
#pragma unroll
            for (int q = 0; q < 4; ++q) d += S.scratch[(q * UU + u) * 2 + r];
            float dec = expf(-fmaxf(d, 0.f));
            dec_s[u * 2 + r] = dec;
            dh_s[u * 2 + r]  = dec * h_s[u * 2 + r];
        } else {
            const int idx = tid & 255;
            if (idx < 128) {
                const int r = idx >> 6, f = idx & 63;
                float zc = S.bcorr[f];
#pragma unroll
                for (int q = 0; q < 8; ++q) zc += S.scratch[2048 + (q * FF + f) * 2 + r];
                zc_s[f * 2 + r] = zc;
                out[((size_t)t * BB + (b0 + r)) * (5 * FF) + FF + f] = zc;
            }
        }
        __syncthreads();

        // ================= S4: beta partials: [m|decay] @ w_concat (streamed) =================
        {
            const int g = tid >> 5;       // 0..15, K=192 split into 12 each
            const int k0 = g * 12;
            float a00 = 0.f, a01 = 0.f, a10 = 0.f, a11 = 0.f;
#pragma unroll
            for (int i = 0; i < 12; ++i) {
                int k = k0 + i;
                float2 w = *reinterpret_cast<const float2*>(w_concat + (size_t)k * FF + f0);
                float2 a = (k < FF) ? S.mm2[k] : S.decay2[k - FF];
                a00 += w.x * a.x; a01 += w.x * a.y;
                a10 += w.y * a.x; a11 += w.y * a.y;
            }
            *reinterpret_cast<float4*>(&S.scratch[(g * FF + f0) * 2]) =
                make_float4(a00, a01, a10, a11);
        }
        __syncthreads();

        // ================= S5: beta combine, c =================
        if (tid < 128) {
            const int r = tid >> 6, f = tid & 63;
            float s = bcc;
#pragma unroll
            for (int g = 0; g < 16; ++g) s += S.scratch[(g * FF + f) * 2 + r];
            float beta = sigmoidf_(s);
            float zcv = zc_s[f * 2 + r];
            float xr  = xreg_s[f * 2 + r];
            float ct  = beta * zcv + (1.f - beta) * xr;
            float m   = mm_s[f * 2 + r];
            float c   = m * xcur_s[f * 2 + r] + (1.f - m) * ct;
            cm_s[f * 2 + r] = c;   // c half of cm
            out[((size_t)t * BB + (b0 + r)) * (5 * FF) + 2 * FF + f] = c;
        }
        __syncthreads();

        // ================= S6: z / r gate partials =================
        {
            const int g = tid >> 6;             // 0..7
            const int gate = g >> 2, kq = g & 3;
            float a00 = 0.f, a01 = 0.f, a10 = 0.f, a11 = 0.f;
            if (gate == 0) {
                if (kq < 2) {                   // dh @ u_update (smem)
                    const int k0 = kq * 64;
#pragma unroll 16
                    for (int i = 0; i < 64; ++i) {
                        float2 w = *reinterpret_cast<const float2*>(&S.u_upd[(k0 + i) * UU + u0]);
                        float2 a = S.dh2[k0 + i];
                        a00 += w.x * a.x; a01 += w.x * a.y;
                        a10 += w.y * a.x; a11 += w.y * a.y;
                    }
                } else {                        // cm @ w_update (smem)
                    const int k0 = (kq - 2) * 64;
#pragma unroll 16
                    for (int i = 0; i < 64; ++i) {
                        float2 w = *reinterpret_cast<const float2*>(&S.w_upd[(k0 + i) * UU + u0]);
                        float2 a = S.cm2[k0 + i];
                        a00 += w.x * a.x; a01 += w.x * a.y;
                        a10 += w.y * a.x; a11 += w.y * a.y;
                    }
                }
            } else {
                if (kq < 2) {                   // dh @ u_reset (smem)
                    const int k0 = kq * 64;
#pragma unroll 16
                    for (int i = 0; i < 64; ++i) {
                        float2 w = *reinterpret_cast<const float2*>(&S.u_rst[(k0 + i) * UU + u0]);
                        float2 a = S.dh2[k0 + i];
                        a00 += w.x * a.x; a01 += w.x * a.y;
                        a10 += w.y * a.x; a11 += w.y * a.y;
                    }
                } else {                        // cm @ w_reset (streamed L2, unique per CTA)
                    const int k0 = (kq - 2) * 64;
#pragma unroll 16
                    for (int i = 0; i < 64; ++i) {
                        float2 w = *reinterpret_cast<const float2*>(w_reset + (size_t)(k0 + i) * UU + u0);
                        float2 a = S.cm2[k0 + i];
                        a00 += w.x * a.x; a01 += w.x * a.y;
                        a10 += w.y * a.x; a11 += w.y * a.y;
                    }
                }
            }
            *reinterpret_cast<float4*>(&S.scratch[(g * UU + u0) * 2]) =
                make_float4(a00, a01, a10, a11);
        }
        __syncthreads();

        // ================= S7: z, r; rg = r*dh =================
        if (tid < 256) {
            const int r = tid >> 7, u = tid & 127;
            float az = bupd, ar = brst;
#pragma unroll
            for (int g = 0; g < 4; ++g) az += S.scratch[(g * UU + u) * 2 + r];
#pragma unroll
            for (int g = 4; g < 8; ++g) ar += S.scratch[(g * UU + u) * 2 + r];
            float z  = sigmoidf_(az);
            float rr = sigmoidf_(ar);
            zb_s[u * 2 + r] = z;
            rg_s[u * 2 + r] = rr * dh_s[u * 2 + r];
        }
        __syncthreads();

        // ================= S8: h_hat partials =================
        {
            const int g = tid >> 6;             // 0..7
            float a00 = 0.f, a01 = 0.f, a10 = 0.f, a11 = 0.f;
            if (g < 4) {                        // rg @ u_update (smem), K-quarter
                const int k0 = g * 32;
#pragma unroll 16
                for (int i = 0; i < 32; ++i) {
                    float2 w = *reinterpret_cast<const float2*>(&S.u_upd[(k0 + i) * UU + u0]);
                    float2 a = S.rg2[k0 + i];
                    a00 += w.x * a.x; a01 += w.x * a.y;
                    a10 += w.y * a.x; a11 += w.y * a.y;
                }
            } else {                            // cm @ w_value_mask (streamed, unique)
                const int k0 = (g - 4) * 32;
#pragma unroll 16
                for (int i = 0; i < 32; ++i) {
                    float2 w = *reinterpret_cast<const float2*>(w_value_mask + (size_t)(k0 + i) * UU + u0);
                    float2 a = S.cm2[k0 + i];
                    a00 += w.x * a.x; a01 += w.x * a.y;
                    a10 += w.y * a.x; a11 += w.y * a.y;
                }
            }
            *reinterpret_cast<float4*>(&S.scratch[(g * UU + u0) * 2]) =
                make_float4(a00, a01, a10, a11);
        }
        __syncthreads();

        // ================= S9: h update =================
        if (tid < 256) {
            const int r = tid >> 7, u = tid & 127;
            float s = bvm;
#pragma unroll
            for (int g = 0; g < 8; ++g) s += S.scratch[(g * UU + u) * 2 + r];
            float hh = tanhf(s);
            float z = zb_s[u * 2 + r];
            float hv = h_s[u * 2 + r];
            h_s[u * 2 + r] = (1.f - z) * hv + z * hh;
        }
        __syncthreads();
    }

    // ---- epilogue: final carries ----
    if (tid < 256) {
        const int r = tid >> 7, u = tid & 127;
        out[OFF_H + (size_t)(b0 + r) * UU + u] = h_s[u * 2 + r];
    }
    if (tid < 128) {
        const int r = tid >> 6, f = tid & 63;
        out[OFF_TS + (size_t)(b0 + r) * FF + f] = ts_s[f * 2 + r];
        out[OFF_DT + (size_t)(b0 + r) * FF + f] = dtv_s[f * 2 + r];
    }
}

extern "C" void kernel_launch(void* const* d_in, const int* in_sizes, int n_in,
                              void* d_out, int out_size) {
    const float* inputs        = (const float*)d_in[0];
    const float* h0            = (const float*)d_in[1];
    const float* ts0           = (const float*)d_in[2];
    const float* dt0           = (const float*)d_in[3];
    const float* w_regression  = (const float*)d_in[4];
    const float* b_regression  = (const float*)d_in[5];
    const float* w_controleur  = (const float*)d_in[6];
    const float* b_controleur  = (const float*)d_in[7];
    const float* w_delta       = (const float*)d_in[8];
    const float* b_delta       = (const float*)d_in[9];
    const float* w_value_mask  = (const float*)d_in[10];
    const float* b_value_mask  = (const float*)d_in[11];
    const float* w_corr        = (const float*)d_in[12];
    const float* b_corr        = (const float*)d_in[13];
    const float* w_concat      = (const float*)d_in[14];
    const float* b_concat      = (const float*)d_in[15];
    const float* u_update      = (const float*)d_in[16];
    const float* w_update      = (const float*)d_in[17];
    const float* b_update      = (const float*)d_in[18];
    const float* u_reset       = (const float*)d_in[19];
    const float* w_reset       = (const float*)d_in[20];
    const float* b_reset       = (const float*)d_in[21];
    float* out = (float*)d_out;

    cudaFuncSetAttribute(padd_gru_kernel,
                         cudaFuncAttributeMaxDynamicSharedMemorySize,
                         (int)sizeof(Smem));
    padd_gru_kernel<<<NCTA, NTHREADS, sizeof(Smem)>>>(
        inputs, h0, ts0, dt0,
        w_regression, b_regression, w_controleur, b_controleur,
        w_delta, b_delta, w_value_mask, b_value_mask,
        w_corr, b_corr, w_concat, b_concat,
        u_update, w_update, b_update,
        u_reset, w_reset, b_reset,
        out);
}

// round 11
// speedup vs baseline: 2.6679x; 1.1106x over previous
#include <cuda_runtime.h>
#include <cstddef>

// Problem constants
#define TT 512
#define BB 256
#define FF 64
#define UU 128
#define NR 2              // batch rows per CTA
#define NCTA (BB / NR)    // 128 CTAs
#define NTHREADS 512

// Output layout: out_seq (T,B,5F) then hT (B,U) then tsT (B,F) then dtT (B,F)
#define OFF_H  ((size_t)TT * BB * 5 * FF)
#define OFF_TS (OFF_H + (size_t)BB * UU)
#define OFF_DT (OFF_TS + (size_t)BB * FF)

// scratch regions (float offsets into S.scratch)
#define SCR_R1 0        // 2048 floats: T0 S0 partials / T2 wd+zcorr / T8 rg partials
#define SCR_B  2048     // 3072 floats: gate-mat m-half (T1) + c-half accum (T6); gm2=w_vm read at T9
#define SCR_E  5120     // 1024 floats: w_concat m-half (T2) + decay-half accum (T4)
#define SCR_F  6144     // 3072 floats: dh@u_update / dh@u_reset partials (T4->T7)
#define SCR_TOTAL 9216

struct Smem {
    float u_upd[UU * UU];     // u_update  128x128 (used T4 + T8)
    float w_upd[UU * UU];     // w_update  128x128 (m-half T1, c-half T6)
    float bctl[FF];
    float bcorr[FF];
    // row-interleaved state: [dim] -> {row0, row1}
    float2 h2[UU];
    float2 dh2[UU];
    float2 decay2[UU];
    float2 rg2[UU];
    float2 zbuf2[UU];
    float2 ts2[FF];
    float2 dtv2[FF];
    float2 xreg2[FF];
    float2 xcur2[FF];
    float2 mm2[FF];
    float2 zc2[FF];
    float2 cc2[FF];           // c only
    float xbuf[2][NR][5 * FF];
    float scratch[SCR_TOTAL];
};

__device__ __forceinline__ float sigmoidf_(float x) {
    return 1.0f / (1.0f + expf(-x));
}

#define FMA8(w4, a2, p0, p1)                                            \
    p0.x += (w4).x * (a2).x; p0.y += (w4).y * (a2).x;                   \
    p0.z += (w4).z * (a2).x; p0.w += (w4).w * (a2).x;                   \
    p1.x += (w4).x * (a2).y; p1.y += (w4).y * (a2).y;                   \
    p1.z += (w4).z * (a2).y; p1.w += (w4).w * (a2).y;

__global__ void __launch_bounds__(NTHREADS, 1)
padd_gru_kernel(const float* __restrict__ inputs,
                const float* __restrict__ h0,
                const float* __restrict__ ts0,
                const float* __restrict__ dt0,
                const float* __restrict__ w_regression,
                const float* __restrict__ b_regression,
                const float* __restrict__ w_controleur,
                const float* __restrict__ b_controleur,
                const float* __restrict__ w_delta,
                const float* __restrict__ b_delta,
                const float* __restrict__ w_value_mask,
                const float* __restrict__ b_value_mask,
                const float* __restrict__ w_corr,
                const float* __restrict__ b_corr,
                const float* __restrict__ w_concat,
                const float* __restrict__ b_concat,
                const float* __restrict__ u_update,
                const float* __restrict__ w_update,
                const float* __restrict__ b_update,
                const float* __restrict__ u_reset,
                const float* __restrict__ w_reset,
                const float* __restrict__ b_reset,
                float* __restrict__ out)
{
    extern __shared__ float smem_raw[];
    Smem& S = *reinterpret_cast<Smem*>(smem_raw);
    const int tid = threadIdx.x;
    const int b0 = blockIdx.x * NR;

    const int fp = tid & 31;          // f-pair index
    const int f0 = fp * 2;
    const int up = tid & 63;          // u-pair index
    const int u0 = up * 2;

    // ---- prologue: cache gate weights in smem ----
    for (int i = tid; i < UU * UU; i += NTHREADS) S.u_upd[i] = u_update[i];
    for (int i = tid; i < UU * UU; i += NTHREADS) S.w_upd[i] = w_update[i];
    for (int i = tid; i < FF; i += NTHREADS) { S.bctl[i] = b_controleur[i]; S.bcorr[i] = b_corr[i]; }

    // ---- state init (row-interleaved) ----
    if (tid < UU) {
        S.h2[tid] = make_float2(h0[(size_t)b0 * UU + tid], h0[(size_t)(b0 + 1) * UU + tid]);
    } else if (tid < UU + FF) {
        int f = tid - UU;
        S.ts2[f]  = make_float2(ts0[(size_t)b0 * FF + f], ts0[(size_t)(b0 + 1) * FF + f]);
        S.dtv2[f] = make_float2(dt0[(size_t)b0 * FF + f], dt0[(size_t)(b0 + 1) * FF + f]);
    }
    // prefetch x for t=0
    if (tid < 320) {
        int r = tid / 160, c2 = tid - r * 160;
        const float2* src = reinterpret_cast<const float2*>(inputs + ((size_t)(b0 + r) * TT) * (5 * FF));
        reinterpret_cast<float2*>(&S.xbuf[0][r][0])[c2] = src[c2];
    }

    // ---- loop-invariant weight slices in registers ----
    // T0: x_reg / tv matvec. g16 in [0,16): mat = g16>>3, K-eighth = (g16&7)*16
    const int g16 = tid >> 5;
    const int s0_k0 = (g16 & 7) * 16;
    float2 wv[16];
    {
        const float* W = (g16 >> 3) ? w_controleur : w_regression;
#pragma unroll
        for (int i = 0; i < 16; ++i)
            wv[i] = *reinterpret_cast<const float2*>(W + (size_t)(s0_k0 + i) * FF + f0);
    }
    // T2: w_delta matvec for tid<256: K-quarter (tid>>6)&3, 16 rows each
    float2 wd[16];
    if (tid < 256) {
        const int k0 = ((tid >> 6) & 3) * 16;
#pragma unroll
        for (int i = 0; i < 16; ++i)
            wd[i] = *reinterpret_cast<const float2*>(w_delta + (size_t)(k0 + i) * UU + u0);
    }

    const float breg = b_regression[0];
    const float bdel = b_delta[0];
    const float bvm  = b_value_mask[0];
    const float bcc  = b_concat[0];
    const float bupd = b_update[0];
    const float brst = b_reset[0];
    __syncthreads();

    float* const ts_s   = reinterpret_cast<float*>(S.ts2);
    float* const dtv_s  = reinterpret_cast<float*>(S.dtv2);
    float* const xreg_s = reinterpret_cast<float*>(S.xreg2);
    float* const xcur_s = reinterpret_cast<float*>(S.xcur2);
    float* const mm_s   = reinterpret_cast<float*>(S.mm2);
    float* const zc_s   = reinterpret_cast<float*>(S.zc2);
    float* const cc_s   = reinterpret_cast<float*>(S.cc2);
    float* const dec_s  = reinterpret_cast<float*>(S.decay2);
    float* const dh_s   = reinterpret_cast<float*>(S.dh2);
    float* const rg_s   = reinterpret_cast<float*>(S.rg2);
    float* const zb_s   = reinterpret_cast<float*>(S.zbuf2);
    float* const h_s    = reinterpret_cast<float*>(S.h2);

    for (int t = 0; t < TT; ++t) {
        // ========= T0: x_reg / tv partials (reg weights) + x prefetch =========
        {
            float a00 = 0.f, a01 = 0.f, a10 = 0.f, a11 = 0.f;
#pragma unroll
            for (int i = 0; i < 16; ++i) {
                float2 hk = S.h2[s0_k0 + i];
                float2 w = wv[i];
                a00 += w.x * hk.x; a01 += w.x * hk.y;
                a10 += w.y * hk.x; a11 += w.y * hk.y;
            }
            *reinterpret_cast<float4*>(&S.scratch[SCR_R1 + (g16 * FF + f0) * 2]) =
                make_float4(a00, a01, a10, a11);

            if (t + 1 < TT && tid < 320) {
                int r = tid / 160, c2 = tid - r * 160;
                const float2* src = reinterpret_cast<const float2*>(
                    inputs + ((size_t)(b0 + r) * TT + (t + 1)) * (5 * FF));
                reinterpret_cast<float2*>(&S.xbuf[(t + 1) & 1][r][0])[c2] = src[c2];
            }
        }
        __syncthreads();

        // ========= T1: elementwise combine (128) || m-half gate GEMVs (384) =========
        if (tid < 128) {
            const int r = tid >> 6, f = tid & 63;
            float xr = breg, tvs = S.bctl[f];
#pragma unroll
            for (int kq = 0; kq < 8; ++kq) {
                xr  += S.scratch[SCR_R1 + (kq * FF + f) * 2 + r];
                tvs += S.scratch[SCR_R1 + ((8 + kq) * FF + f) * 2 + r];
            }
            float tv = fabsf(tvs);
            const float* xb = S.xbuf[t & 1][r];
            float ti_in = xb[f];
            float x_in  = xb[FF + f];
            float m     = xb[2 * FF + f];
            float dt_in = xb[3 * FF + f];
            float pad   = xb[4 * FF + f];
            float pts = ts_s[f * 2 + r], pdt = dtv_s[f * 2 + r];
            float cand = pts + tv;
            float ti = pad * ti_in + (1.f - pad) * cand;
            ti = (ti <= 100.0f) ? ti : pts;
            float dgen = (cand <= 100.0f) ? tv : pdt;
            float ndt = pad * dt_in + (1.f - pad) * dgen;
            float xc = m * x_in + (1.f - m) * xr;
            ts_s[f * 2 + r]   = ti;
            dtv_s[f * 2 + r]  = ndt;
            xreg_s[f * 2 + r] = xr;
            xcur_s[f * 2 + r] = xc;
            mm_s[f * 2 + r]   = m;
            size_t ob = ((size_t)t * BB + (b0 + r)) * (5 * FF);
            out[ob + f]          = xr;
            out[ob + 3 * FF + f] = ti;
            out[ob + 4 * FF + f] = ndt;
        } else {
            // m-half of w_update (smem) / w_reset (L2) / w_value_mask (L2)
            const int t7  = (tid - 128) & 127;
            const int gm  = (tid - 128) >> 7;   // 0..2 (warp-uniform)
            const int uq  = t7 & 31;
            const int ksl = t7 >> 5;            // 0..3, 16 k each
            const float* xb0 = &S.xbuf[t & 1][0][2 * FF];
            const float* xb1 = &S.xbuf[t & 1][1][2 * FF];
            float4 p0 = make_float4(0.f, 0.f, 0.f, 0.f);
            float4 p1 = make_float4(0.f, 0.f, 0.f, 0.f);
            if (gm == 0) {
#pragma unroll
                for (int i = 0; i < 16; ++i) {
                    int k = ksl * 16 + i;
                    float4 w = *reinterpret_cast<const float4*>(&S.w_upd[(FF + k) * UU + uq * 4]);
                    float2 a = make_float2(xb0[k], xb1[k]);
                    FMA8(w, a, p0, p1);
                }
            } else {
                const float* W = (gm == 1) ? w_reset : w_value_mask;
#pragma unroll
                for (int i = 0; i < 16; ++i) {
                    int k = ksl * 16 + i;
                    float4 w = *reinterpret_cast<const float4*>(&W[(size_t)(FF + k) * UU + uq * 4]);
                    float2 a = make_float2(xb0[k], xb1[k]);
                    FMA8(w, a, p0, p1);
                }
            }
            float* dst = &S.scratch[SCR_B + (((gm * 4 + ksl) * 32 + uq) * 2) * 4];
            *reinterpret_cast<float4*>(dst)     = p0;
            *reinterpret_cast<float4*>(dst + 4) = p1;
        }
        __syncthreads();

        // ========= T2: w_delta (256, reg wts) || z_corr (128) || w_concat m-half (128) =========
        if (tid < 256) {
            const int q = (tid >> 6) & 3;
            float a00 = 0.f, a01 = 0.f, a10 = 0.f, a11 = 0.f;
#pragma unroll
            for (int i = 0; i < 16; ++i) {
                float2 dk = S.dtv2[q * 16 + i];
                float2 w = wd[i];
                a00 += w.x * dk.x; a01 += w.x * dk.y;
                a10 += w.y * dk.x; a11 += w.y * dk.y;
            }
            *reinterpret_cast<float4*>(&S.scratch[SCR_R1 + (q * UU + u0) * 2]) =
                make_float4(a00, a01, a10, a11);
        } else if (tid < 384) {
            const int t7 = tid - 256;
            const int fq = t7 & 15, ksl = t7 >> 4;   // 8 ksl x 8 k
            float4 p0 = make_float4(0.f, 0.f, 0.f, 0.f);
            float4 p1 = make_float4(0.f, 0.f, 0.f, 0.f);
#pragma unroll
            for (int i = 0; i < 8; ++i) {
                int k = ksl * 8 + i;
                float4 w = *reinterpret_cast<const float4*>(&w_corr[(size_t)k * FF + fq * 4]);
                if ((k >> 2) == fq) reinterpret_cast<float*>(&w)[k & 3] = 0.f;  // off-diag mask
                float2 a = S.xcur2[k];
                FMA8(w, a, p0, p1);
            }
            float* dst = &S.scratch[SCR_R1 + 1024 + ((ksl * 16 + fq) * 2) * 4];
            *reinterpret_cast<float4*>(dst)     = p0;
            *reinterpret_cast<float4*>(dst + 4) = p1;
        } else {
            const int t7 = tid - 384;
            const int fq = t7 & 15, ksl = t7 >> 4;   // 8 ksl x 8 k over K=0..63 (m rows)
            float4 p0 = make_float4(0.f, 0.f, 0.f, 0.f);
            float4 p1 = make_float4(0.f, 0.f, 0.f, 0.f);
#pragma unroll
            for (int i = 0; i < 8; ++i) {
                int k = ksl * 8 + i;
                float4 w = *reinterpret_cast<const float4*>(&w_concat[(size_t)k * FF + fq * 4]);
                float2 a = S.mm2[k];
                FMA8(w, a, p0, p1);
            }
            float* dst = &S.scratch[SCR_E + ((ksl * 16 + fq) * 2) * 4];
            *reinterpret_cast<float4*>(dst)     = p0;
            *reinterpret_cast<float4*>(dst + 4) = p1;
        }
        __syncthreads();

        // ========= T3: decay & dh (256) || z_corr combine (128) =========
        if (tid < 256) {
            const int r = tid >> 7, u = tid & 127;
            float d = bdel;
#pragma unroll
            for (int q = 0; q < 4; ++q) d += S.scratch[SCR_R1 + (q * UU + u) * 2 + r];
            float dec = expf(-fmaxf(d, 0.f));
            dec_s[u * 2 + r] = dec;
            dh_s[u * 2 + r]  = dec * h_s[u * 2 + r];
        } else if (tid < 384) {
            const int idx = tid - 256;
            const int r = idx >> 6, f = idx & 63;
            const int fq = f >> 2, c = f & 3;
            float zc = S.bcorr[f];
#pragma unroll
            for (int ksl = 0; ksl < 8; ++ksl)
                zc += S.scratch[SCR_R1 + 1024 + ((ksl * 16 + fq) * 2 + r) * 4 + c];
            zc_s[f * 2 + r] = zc;
            out[((size_t)t * BB + (b0 + r)) * (5 * FF) + FF + f] = zc;
        }
        __syncthreads();

        // ========= T4: dh@u_update / dh@u_reset (384) || decay@w_concat (128, accum E) =========
        if (tid < 384) {
            const int gate = (tid >= 192) ? 1 : 0;   // warp-uniform (192 = 6 warps)
            const int w = tid - gate * 192;
            const int uq = w & 31;
            const int ksl = w >> 5;                  // 0..5
            const int k0 = (ksl * UU) / 6, k1 = ((ksl + 1) * UU) / 6;
            float4 p0 = make_float4(0.f, 0.f, 0.f, 0.f);
            float4 p1 = make_float4(0.f, 0.f, 0.f, 0.f);
            if (gate == 0) {
#pragma unroll 4
                for (int k = k0; k < k1; ++k) {
                    float4 w4 = *reinterpret_cast<const float4*>(&S.u_upd[k * UU + uq * 4]);
                    float2 a = S.dh2[k];
                    FMA8(w4, a, p0, p1);
                }
            } else {
#pragma unroll 4
                for (int k = k0; k < k1; ++k) {
                    float4 w4 = *reinterpret_cast<const float4*>(&u_reset[(size_t)k * UU + uq * 4]);
                    float2 a = S.dh2[k];
                    FMA8(w4, a, p0, p1);
                }
            }
            float* dst = &S.scratch[SCR_F + (((gate * 6 + ksl) * 32 + uq) * 2) * 4];
            *reinterpret_cast<float4*>(dst)     = p0;
            *reinterpret_cast<float4*>(dst + 4) = p1;
        } else {
            const int t7 = tid - 384;
            const int fq = t7 & 15, ksl = t7 >> 4;   // 8 ksl x 16 k over K=0..127 (decay rows)
            float* dst = &S.scratch[SCR_E + ((ksl * 16 + fq) * 2) * 4];
            float4 p0 = *reinterpret_cast<float4*>(dst);
            float4 p1 = *reinterpret_cast<float4*>(dst + 4);
#pragma unroll 8
            for (int i = 0; i < 16; ++i) {
                int k = ksl * 16 + i;
                float4 w = *reinterpret_cast<const float4*>(&w_concat[(size_t)(FF + k) * FF + fq * 4]);
                float2 a = S.decay2[k];
                FMA8(w, a, p0, p1);
            }
            *reinterpret_cast<float4*>(dst)     = p0;
            *reinterpret_cast<float4*>(dst + 4) = p1;
        }
        __syncthreads();

        // ========= T5: beta combine, c =========
        if (tid < 128) {
            const int r = tid >> 6, f = tid & 63;
            const int fq = f >> 2, c = f & 3;
            float s = bcc;
#pragma unroll
            for (int ksl = 0; ksl < 8; ++ksl)
                s += S.scratch[SCR_E + ((ksl * 16 + fq) * 2 + r) * 4 + c];
            float beta = sigmoidf_(s);
            float zcv = zc_s[f * 2 + r];
            float xr  = xreg_s[f * 2 + r];
            float ct  = beta * zcv + (1.f - beta) * xr;
            float m   = mm_s[f * 2 + r];
            float cv  = m * xcur_s[f * 2 + r] + (1.f - m) * ct;
            cc_s[f * 2 + r] = cv;
            out[((size_t)t * BB + (b0 + r)) * (5 * FF) + 2 * FF + f] = cv;
        }
        __syncthreads();

        // ========= T6: c-half of w_update/w_reset/w_value_mask, accumulate into B =========
        if (tid < 384) {
            const int gm  = tid >> 7;      // 0..2
            const int t7  = tid & 127;
            const int uq  = t7 & 31;
            const int ksl = t7 >> 5;       // 0..3, 16 k over K=0..63 (c rows)
            float4 p0 = make_float4(0.f, 0.f, 0.f, 0.f);
            float4 p1 = make_float4(0.f, 0.f, 0.f, 0.f);
            if (gm == 0) {
#pragma unroll
                for (int i = 0; i < 16; ++i) {
                    int k = ksl * 16 + i;
                    float4 w = *reinterpret_cast<const float4*>(&S.w_upd[k * UU + uq * 4]);
                    float2 a = S.cc2[k];
                    FMA8(w, a, p0, p1);
                }
            } else {
                const float* W = (gm == 1) ? w_reset : w_value_mask;
#pragma unroll
                for (int i = 0; i < 16; ++i) {
                    int k = ksl * 16 + i;
                    float4 w = *reinterpret_cast<const float4*>(&W[(size_t)k * UU + uq * 4]);
                    float2 a = S.cc2[k];
                    FMA8(w, a, p0, p1);
                }
            }
            float* dst = &S.scratch[SCR_B + (((gm * 4 + ksl) * 32 + uq) * 2) * 4];
            float4 q0 = *reinterpret_cast<float4*>(dst);
            float4 q1 = *reinterpret_cast<float4*>(dst + 4);
            q0.x += p0.x; q0.y += p0.y; q0.z += p0.z; q0.w += p0.w;
            q1.x += p1.x; q1.y += p1.y; q1.z += p1.z; q1.w += p1.w;
            *reinterpret_cast<float4*>(dst)     = q0;
            *reinterpret_cast<float4*>(dst + 4) = q1;
        }
        __syncthreads();

        // ========= T7: z, r combine; rg = r*dh (all 512) =========
        {
            const int g = tid >> 8;            // 0=update, 1=reset
            const int r = (tid >> 7) & 1;
            const int u = tid & 127;
            const int uq = u >> 2, c = u & 3;
            float s = g ? brst : bupd;
#pragma unroll
            for (int ksl = 0; ksl < 6; ++ksl)
                s += S.scratch[SCR_F + (((g * 6 + ksl) * 32 + uq) * 2 + r) * 4 + c];
#pragma unroll
            for (int ksl = 0; ksl < 4; ++ksl)
                s += S.scratch[SCR_B + (((g * 4 + ksl) * 32 + uq) * 2 + r) * 4 + c];
            float sg = sigmoidf_(s);
            if (g == 0) zb_s[u * 2 + r] = sg;
            else        rg_s[u * 2 + r] = sg * dh_s[u * 2 + r];
        }
        __syncthreads();

        // ========= T8: rg @ u_update partials (all 512) =========
        {
            const int ksl = tid >> 6;          // 0..7, 16 k each
            float a00 = 0.f, a01 = 0.f, a10 = 0.f, a11 = 0.f;
#pragma unroll
            for (int i = 0; i < 16; ++i) {
                int k = ksl * 16 + i;
                float2 w = *reinterpret_cast<const float2*>(&S.u_upd[k * UU + u0]);
                float2 a = S.rg2[k];
                a00 += w.x * a.x; a01 += w.x * a.y;
                a10 += w.y * a.x; a11 += w.y * a.y;
            }
            *reinterpret_cast<float4*>(&S.scratch[SCR_R1 + (ksl * UU + u0) * 2]) =
                make_float4(a00, a01, a10, a11);
        }
        __syncthreads();

        // ========= T9: h_hat combine + h update =========
        if (tid < 256) {
            const int r = tid >> 7, u = tid & 127;
            const int uq = u >> 2, c = u & 3;
            float s = bvm;
#pragma unroll
            for (int ksl = 0; ksl < 8; ++ksl)
                s += S.scratch[SCR_R1 + (ksl * UU + u) * 2 + r];
#pragma unroll
            for (int ksl = 0; ksl < 4; ++ksl)
                s += S.scratch[SCR_B + (((2 * 4 + ksl) * 32 + uq) * 2 + r) * 4 + c];
            float hh = tanhf(s);
            float z = zb_s[u * 2 + r];
            float hv = h_s[u * 2 + r];
            h_s[u * 2 + r] = (1.f - z) * hv + z * hh;
        }
        __syncthreads();
    }

    // ---- epilogue: final carries ----
    if (tid < 256) {
        const int r = tid >> 7, u = tid & 127;
        out[OFF_H + (size_t)(b0 + r) * UU + u] = h_s[u * 2 + r];
    }
    if (tid < 128) {
        const int r = tid >> 6, f = tid & 63;
        out[OFF_TS + (size_t)(b0 + r) * FF + f] = ts_s[f * 2 + r];
        out[OFF_DT + (size_t)(b0 + r) * FF + f] = dtv_s[f * 2 + r];
    }
}

extern "C" void kernel_launch(void* const* d_in, const int* in_sizes, int n_in,
                              void* d_out, int out_size) {
    const float* inputs        = (const float*)d_in[0];
    const float* h0            = (const float*)d_in[1];
    const float* ts0           = (const float*)d_in[2];
    const float* dt0           = (const float*)d_in[3];
    const float* w_regression  = (const float*)d_in[4];
    const float* b_regression  = (const float*)d_in[5];
    const float* w_controleur  = (const float*)d_in[6];
    const float* b_controleur  = (const float*)d_in[7];
    const float* w_delta       = (const float*)d_in[8];
    const float* b_delta       = (const float*)d_in[9];
    const float* w_value_mask  = (const float*)d_in[10];
    const float* b_value_mask  = (const float*)d_in[11];
    const float* w_corr        = (const float*)d_in[12];
    const float* b_corr        = (const float*)d_in[13];
    const float* w_concat      = (const float*)d_in[14];
    const float* b_concat      = (const float*)d_in[15];
    const float* u_update      = (const float*)d_in[16];
    const float* w_update      = (const float*)d_in[17];
    const float* b_update      = (const float*)d_in[18];
    const float* u_reset       = (const float*)d_in[19];
    const float* w_reset       = (const float*)d_in[20];
    const float* b_reset       = (const float*)d_in[21];
    float* out = (float*)d_out;

    cudaFuncSetAttribute(padd_gru_kernel,
                         cudaFuncAttributeMaxDynamicSharedMemorySize,
                         (int)sizeof(Smem));
    padd_gru_kernel<<<NCTA, NTHREADS, sizeof(Smem)>>>(
        inputs, h0, ts0, dt0,
        w_regression, b_regression, w_controleur, b_controleur,
        w_delta, b_delta, w_value_mask, b_value_mask,
        w_corr, b_corr, w_concat, b_concat,
        u_update, w_update, b_update,
        u_reset, w_reset, b_reset,
        out);
}

// round 15
// speedup vs baseline: 3.1381x; 1.1762x over previous
#include <cuda_runtime.h>
#include <cstddef>

// Problem constants
#define TT 512
#define BB 256
#define FF 64
#define UU 128
#define NR 2              // batch rows per CTA
#define NCTA (BB / NR)    // 128 CTAs
#define NTHREADS 512

// Output layout: out_seq (T,B,5F) then hT (B,U) then tsT (B,F) then dtT (B,F)
#define OFF_H  ((size_t)TT * BB * 5 * FF)
#define OFF_TS (OFF_H + (size_t)BB * UU)
#define OFF_DT (OFF_TS + (size_t)BB * FF)

// scratch regions (float offsets). Each slot = 8 floats: row0 float4 | row1 float4.
#define SCR_S0 0        // 2048: S0 partials (P). Reused late in step for J (rg@u_upd).
#define SCR_WD 2048     // 2048: w_delta partials (P)
#define SCR_F  4096     // 2048: dh@u_update / dh@u_reset partials (P)
#define SCR_B  6144     // 1536: gate m-half (Q phase1) + c-half accum (Q H): (gm,kh,uq)
#define SCR_D  7680     // 1024: z_corr partials (Q)
#define SCR_E  8704     // 512:  w_concat m-half (Q)
#define SCR_E2 9216     // 1024: w_concat decay-half (Q)
#define SCR_TOTAL 10240

struct Smem {
    float u_upd[UU * UU];     // u_update  128x128 (P: F gate0, J)
    float w_upd[UU * UU];     // w_update  128x128 (Q: B m-half, H c-half)
    float bctl[FF];
    float bcorr[FF];
    // row-interleaved state: [dim] -> {row0, row1}
    float2 h2[UU];
    float2 dh2[UU];
    float2 decay2[UU];
    float2 rg2[UU];
    float2 zbuf2[UU];
    float2 ts2[FF];
    float2 dtv2[FF];
    float2 xreg2[FF];
    float2 xcur2[FF];
    float2 mm2[FF];
    float2 cc2[FF];
    float xbuf[2][NR][5 * FF]; // double-buffered inputs
    float scratch[SCR_TOTAL];
};

__device__ __forceinline__ float sigmoidf_(float x) {
    return 1.0f / (1.0f + expf(-x));
}

#define FMA8(w4, a2, p0, p1)                                            \
    p0.x += (w4).x * (a2).x; p0.y += (w4).y * (a2).x;                   \
    p0.z += (w4).z * (a2).x; p0.w += (w4).w * (a2).x;                   \
    p1.x += (w4).x * (a2).y; p1.y += (w4).y * (a2).y;                   \
    p1.z += (w4).z * (a2).y; p1.w += (w4).w * (a2).y;

#define BARS(id, count) asm volatile("bar.sync %0, %1;"   :: "r"(id), "r"(count) : "memory")
#define BARA(id, count) asm volatile("bar.arrive %0, %1;" :: "r"(id), "r"(count) : "memory")

__global__ void __launch_bounds__(NTHREADS, 1)
padd_gru_kernel(const float* __restrict__ inputs,
                const float* __restrict__ h0,
                const float* __restrict__ ts0,
                const float* __restrict__ dt0,
                const float* __restrict__ w_regression,
                const float* __restrict__ b_regression,
                const float* __restrict__ w_controleur,
                const float* __restrict__ b_controleur,
                const float* __restrict__ w_delta,
                const float* __restrict__ b_delta,
                const float* __restrict__ w_value_mask,
                const float* __restrict__ b_value_mask,
                const float* __restrict__ w_corr,
                const float* __restrict__ b_corr,
                const float* __restrict__ w_concat,
                const float* __restrict__ b_concat,
                const float* __restrict__ u_update,
                const float* __restrict__ w_update,
                const float* __restrict__ b_update,
                const float* __restrict__ u_reset,
                const float* __restrict__ w_reset,
                const float* __restrict__ b_reset,
                float* __restrict__ out)
{
    extern __shared__ float smem_raw[];
    Smem& S = *reinterpret_cast<Smem*>(smem_raw);
    const int tid = threadIdx.x;
    const int b0 = blockIdx.x * NR;

    // ---- prologue: cache u_update + w_update in smem ----
    for (int i = tid; i < UU * UU; i += NTHREADS) S.u_upd[i] = u_update[i];
    for (int i = tid; i < UU * UU; i += NTHREADS) S.w_upd[i] = w_update[i];
    for (int i = tid; i < FF; i += NTHREADS) { S.bctl[i] = b_controleur[i]; S.bcorr[i] = b_corr[i]; }

    // ---- state init (row-interleaved) ----
    if (tid < UU) {
        S.h2[tid] = make_float2(h0[(size_t)b0 * UU + tid], h0[(size_t)(b0 + 1) * UU + tid]);
    } else if (tid < UU + FF) {
        int f = tid - UU;
        S.ts2[f]  = make_float2(ts0[(size_t)b0 * FF + f], ts0[(size_t)(b0 + 1) * FF + f]);
        S.dtv2[f] = make_float2(dt0[(size_t)b0 * FF + f], dt0[(size_t)(b0 + 1) * FF + f]);
    }
    // prefetch x for t=0
    if (tid < 320) {
        int r = tid / 160, c2 = tid - r * 160;
        const float2* src = reinterpret_cast<const float2*>(inputs + ((size_t)(b0 + r) * TT) * (5 * FF));
        reinterpret_cast<float2*>(&S.xbuf[0][0][0])[r * 160 + c2] = src[c2];
    }

    const float breg = b_regression[0];
    const float bdel = b_delta[0];
    const float bvm  = b_value_mask[0];
    const float bcc  = b_concat[0];
    const float bupd = b_update[0];
    const float brst = b_reset[0];
    __syncthreads();

    float* const ts_s   = reinterpret_cast<float*>(S.ts2);
    float* const dtv_s  = reinterpret_cast<float*>(S.dtv2);
    float* const xreg_s = reinterpret_cast<float*>(S.xreg2);
    float* const xcur_s = reinterpret_cast<float*>(S.xcur2);
    float* const mm_s   = reinterpret_cast<float*>(S.mm2);
    float* const cc_s   = reinterpret_cast<float*>(S.cc2);
    float* const dec_s  = reinterpret_cast<float*>(S.decay2);
    float* const dh_s   = reinterpret_cast<float*>(S.dh2);
    float* const rg_s   = reinterpret_cast<float*>(S.rg2);
    float* const zb_s   = reinterpret_cast<float*>(S.zbuf2);
    float* const h_s    = reinterpret_cast<float*>(S.h2);

    for (int t = 0; t < TT; ++t) {
        if (tid < 256) {
            // ================= GROUP P (warps 0-7): recurrence critical path =================
            const int t7 = tid & 127;

            // --- P1: S0 partials: h @ w_regression / w_controleur ---
            {
                const int m = tid >> 7;                 // 0: regression, 1: controleur
                const int fq = t7 & 15, ksl = t7 >> 4;  // 16 quads x 8 kslices(16k)
                const float* W = m ? w_controleur : w_regression;
                float4 p0 = make_float4(0.f, 0.f, 0.f, 0.f);
                float4 p1 = make_float4(0.f, 0.f, 0.f, 0.f);
#pragma unroll
                for (int i = 0; i < 16; ++i) {
                    int k = ksl * 16 + i;
                    float4 w = *reinterpret_cast<const float4*>(&W[(size_t)k * FF + fq * 4]);
                    float2 a = S.h2[k];
                    FMA8(w, a, p0, p1);
                }
                float* dst = &S.scratch[SCR_S0 + ((m * 8 + ksl) * 16 + fq) * 8];
                *reinterpret_cast<float4*>(dst)     = p0;
                *reinterpret_cast<float4*>(dst + 4) = p1;
            }
            BARS(1, 256);

            // --- P2: C1 elementwise combine (threads 0..127) ---
            if (tid < 128) {
                const int r = tid >> 6, f = tid & 63;
                const int fq = f >> 2, c = f & 3;
                float xr = breg, tvs = S.bctl[f];
#pragma unroll
                for (int ksl = 0; ksl < 8; ++ksl) {
                    xr  += S.scratch[SCR_S0 + ((ksl) * 16 + fq) * 8 + r * 4 + c];
                    tvs += S.scratch[SCR_S0 + ((8 + ksl) * 16 + fq) * 8 + r * 4 + c];
                }
                float tv = fabsf(tvs);
                const float* xb = S.xbuf[t & 1][r];
                float ti_in = xb[f];
                float x_in  = xb[FF + f];
                float m     = xb[2 * FF + f];
                float dt_in = xb[3 * FF + f];
                float pad   = xb[4 * FF + f];
                float pts = ts_s[f * 2 + r], pdt = dtv_s[f * 2 + r];
                float cand = pts + tv;
                float ti = pad * ti_in + (1.f - pad) * cand;
                ti = (ti <= 100.0f) ? ti : pts;
                float dgen = (cand <= 100.0f) ? tv : pdt;
                float ndt = pad * dt_in + (1.f - pad) * dgen;
                float xc = m * x_in + (1.f - m) * xr;
                ts_s[f * 2 + r]   = ti;
                dtv_s[f * 2 + r]  = ndt;
                xreg_s[f * 2 + r] = xr;
                xcur_s[f * 2 + r] = xc;
                mm_s[f * 2 + r]   = m;
                size_t ob = ((size_t)t * BB + (b0 + r)) * (5 * FF);
                out[ob + f]          = xr;
                out[ob + 3 * FF + f] = ti;
                out[ob + 4 * FF + f] = ndt;
            }
            BARA(2, 512);   // hand xcur/mm/xreg to Q
            BARS(4, 256);   // P-internal: dtv visible

            // --- P3: w_delta partials ---
            {
                const int uq = tid & 31, ksl = tid >> 5;   // 0..7, 8 k each
                float4 p0 = make_float4(0.f, 0.f, 0.f, 0.f);
                float4 p1 = make_float4(0.f, 0.f, 0.f, 0.f);
#pragma unroll
                for (int i = 0; i < 8; ++i) {
                    int k = ksl * 8 + i;
                    float4 w = *reinterpret_cast<const float4*>(&w_delta[(size_t)k * UU + uq * 4]);
                    float2 a = S.dtv2[k];
                    FMA8(w, a, p0, p1);
                }
                float* dst = &S.scratch[SCR_WD + (ksl * 32 + uq) * 8];
                *reinterpret_cast<float4*>(dst)     = p0;
                *reinterpret_cast<float4*>(dst + 4) = p1;
            }
            BARS(3, 256);

            // --- P4: decay + dh ---
            {
                const int r = tid >> 7, u = tid & 127;
                const int uq = u >> 2, c = u & 3;
                float d = bdel;
#pragma unroll
                for (int ksl = 0; ksl < 8; ++ksl)
                    d += S.scratch[SCR_WD + (ksl * 32 + uq) * 8 + r * 4 + c];
                float dec = expf(-fmaxf(d, 0.f));
                dec_s[u * 2 + r] = dec;
                dh_s[u * 2 + r]  = dec * h_s[u * 2 + r];
            }
            BARA(5, 384);   // hand decay to Q-high
            BARS(4, 256);   // P-internal: dh visible

            // --- P5: F = dh @ u_update (smem) / dh @ u_reset (L2) ---
            {
                const int gate = tid >> 7;
                const int uq = t7 & 31, ksl = t7 >> 5;  // 0..3, 32 k each
                float4 p0 = make_float4(0.f, 0.f, 0.f, 0.f);
                float4 p1 = make_float4(0.f, 0.f, 0.f, 0.f);
                if (gate == 0) {
#pragma unroll 8
                    for (int i = 0; i < 32; ++i) {
                        int k = ksl * 32 + i;
                        float4 w = *reinterpret_cast<const float4*>(&S.u_upd[k * UU + uq * 4]);
                        float2 a = S.dh2[k];
                        FMA8(w, a, p0, p1);
                    }
                } else {
#pragma unroll 8
                    for (int i = 0; i < 32; ++i) {
                        int k = ksl * 32 + i;
                        float4 w = *reinterpret_cast<const float4*>(&u_reset[(size_t)k * UU + uq * 4]);
                        float2 a = S.dh2[k];
                        FMA8(w, a, p0, p1);
                    }
                }
                float* dst = &S.scratch[SCR_F + ((gate * 4 + ksl) * 32 + uq) * 8];
                *reinterpret_cast<float4*>(dst)     = p0;
                *reinterpret_cast<float4*>(dst + 4) = p1;
            }
            BARS(6, 512);   // wait Q's B+H scratch (and publish F)

            // --- P6: z, r combine; rg = r*dh (both rows per thread) ---
            {
                const int g = tid >> 7;     // 0=update(z), 1=reset(r)
                const int u = tid & 127;
                const int uq = u >> 2, c = u & 3;
                float bias = g ? brst : bupd;
#pragma unroll
                for (int r = 0; r < 2; ++r) {
                    float s = bias;
#pragma unroll
                    for (int ksl = 0; ksl < 4; ++ksl)
                        s += S.scratch[SCR_F + ((g * 4 + ksl) * 32 + uq) * 8 + r * 4 + c];
#pragma unroll
                    for (int kh = 0; kh < 2; ++kh)
                        s += S.scratch[SCR_B + ((g * 2 + kh) * 32 + uq) * 8 + r * 4 + c];
                    float sg = sigmoidf_(s);
                    if (g == 0) zb_s[u * 2 + r] = sg;
                    else        rg_s[u * 2 + r] = sg * dh_s[u * 2 + r];
                }
            }
            BARS(1, 256);

            // --- P7: J = rg @ u_update partials (reuse SCR_S0) ---
            {
                const int uq = tid & 31, ksl = tid >> 5;  // 0..7, 16 k each
                float4 p0 = make_float4(0.f, 0.f, 0.f, 0.f);
                float4 p1 = make_float4(0.f, 0.f, 0.f, 0.f);
#pragma unroll 8
                for (int i = 0; i < 16; ++i) {
                    int k = ksl * 16 + i;
                    float4 w = *reinterpret_cast<const float4*>(&S.u_upd[k * UU + uq * 4]);
                    float2 a = S.rg2[k];
                    FMA8(w, a, p0, p1);
                }
                float* dst = &S.scratch[SCR_S0 + (ksl * 32 + uq) * 8];
                *reinterpret_cast<float4*>(dst)     = p0;
                *reinterpret_cast<float4*>(dst + 4) = p1;
            }
            BARS(3, 256);

            // --- P8: h_hat combine + h update ---
            {
                const int r = tid >> 7, u = tid & 127;
                const int uq = u >> 2, c = u & 3;
                float s = bvm;
#pragma unroll
                for (int ksl = 0; ksl < 8; ++ksl)
                    s += S.scratch[SCR_S0 + (ksl * 32 + uq) * 8 + r * 4 + c];
#pragma unroll
                for (int kh = 0; kh < 2; ++kh)
                    s += S.scratch[SCR_B + ((4 + kh) * 32 + uq) * 8 + r * 4 + c];
                float hh = tanhf(s);
                float z = zb_s[u * 2 + r];
                float hv = h_s[u * 2 + r];
                h_s[u * 2 + r] = (1.f - z) * hv + z * hh;
            }
        } else {
            // ================= GROUP Q (warps 8-15): mask/correlation dataflow =================
            const int tq = tid - 256;

            // --- Q1: prefetch x_{t+1} + m-half gate GEMVs + w_concat m-half ---
            if (t + 1 < TT) {
                const float2* src0 = reinterpret_cast<const float2*>(
                    inputs + ((size_t)b0 * TT + (t + 1)) * (5 * FF));
                const float2* src1 = reinterpret_cast<const float2*>(
                    inputs + ((size_t)(b0 + 1) * TT + (t + 1)) * (5 * FF));
                float2* dst = reinterpret_cast<float2*>(&S.xbuf[(t + 1) & 1][0][0]);
                {
                    int i = tq;                 // 0..255
                    dst[i] = (i < 160) ? src0[i] : src1[i - 160];
                }
                if (tq < 64) {
                    int i = tq + 256;           // 256..319
                    dst[i] = src1[i - 160];
                }
            }
            {
                const float* xb0 = &S.xbuf[t & 1][0][2 * FF];
                const float* xb1 = &S.xbuf[t & 1][1][2 * FF];
                if (tq < 192) {
                    const int gm = tq >> 6;            // 0:w_upd 1:w_reset 2:w_value_mask
                    const int t6 = tq & 63;
                    const int uq = t6 & 31, kh = t6 >> 5;   // 2 khalves x 32 k
                    float4 p0 = make_float4(0.f, 0.f, 0.f, 0.f);
                    float4 p1 = make_float4(0.f, 0.f, 0.f, 0.f);
                    if (gm == 0) {
#pragma unroll 8
                        for (int i = 0; i < 32; ++i) {
                            int k = kh * 32 + i;
                            float4 w = *reinterpret_cast<const float4*>(&S.w_upd[(FF + k) * UU + uq * 4]);
                            float2 a = make_float2(xb0[k], xb1[k]);
                            FMA8(w, a, p0, p1);
                        }
                    } else {
                        const float* W = (gm == 1) ? w_reset : w_value_mask;
#pragma unroll 8
                        for (int i = 0; i < 32; ++i) {
                            int k = kh * 32 + i;
                            float4 w = *reinterpret_cast<const float4*>(&W[(size_t)(FF + k) * UU + uq * 4]);
                            float2 a = make_float2(xb0[k], xb1[k]);
                            FMA8(w, a, p0, p1);
                        }
                    }
                    float* dst = &S.scratch[SCR_B + ((gm * 2 + kh) * 32 + uq) * 8];
                    *reinterpret_cast<float4*>(dst)     = p0;
                    *reinterpret_cast<float4*>(dst + 4) = p1;
                } else {
                    const int tE = tq - 192;
                    const int fq = tE & 15, kq = tE >> 4;   // 0..3, 16 k each
                    float4 p0 = make_float4(0.f, 0.f, 0.f, 0.f);
                    float4 p1 = make_float4(0.f, 0.f, 0.f, 0.f);
#pragma unroll 8
                    for (int i = 0; i < 16; ++i) {
                        int k = kq * 16 + i;
                        float4 w = *reinterpret_cast<const float4*>(&w_concat[(size_t)k * FF + fq * 4]);
                        float2 a = make_float2(xb0[k], xb1[k]);
                        FMA8(w, a, p0, p1);
                    }
                    float* dst = &S.scratch[SCR_E + (kq * 16 + fq) * 8];
                    *reinterpret_cast<float4*>(dst)     = p0;
                    *reinterpret_cast<float4*>(dst + 4) = p1;
                }
            }
            BARS(2, 512);   // wait P's C1 (xcur/mm/xreg ready)

            // --- Q2: z_corr (warps 8-11) || decay-half of w_concat (warps 12-15) ---
            if (tq < 128) {
                const int fq = tq & 15, ksl = tq >> 4;   // 0..7, 8 k each
                float4 p0 = make_float4(0.f, 0.f, 0.f, 0.f);
                float4 p1 = make_float4(0.f, 0.f, 0.f, 0.f);
#pragma unroll
                for (int i = 0; i < 8; ++i) {
                    int k = ksl * 8 + i;
                    float4 w = *reinterpret_cast<const float4*>(&w_corr[(size_t)k * FF + fq * 4]);
                    if ((k >> 2) == fq) reinterpret_cast<float*>(&w)[k & 3] = 0.f;  // off-diag mask
                    float2 a = S.xcur2[k];
                    FMA8(w, a, p0, p1);
                }
                float* dst = &S.scratch[SCR_D + (ksl * 16 + fq) * 8];
                *reinterpret_cast<float4*>(dst)     = p0;
                *reinterpret_cast<float4*>(dst + 4) = p1;
            } else {
                BARS(5, 384);   // wait P's decay
                const int tE = tq - 128;
                const int fq = tE & 15, ksl = tE >> 4;   // 0..7, 16 k each
                float4 p0 = make_float4(0.f, 0.f, 0.f, 0.f);
                float4 p1 = make_float4(0.f, 0.f, 0.f, 0.f);
#pragma unroll 8
                for (int i = 0; i < 16; ++i) {
                    int k = ksl * 16 + i;
                    float4 w = *reinterpret_cast<const float4*>(&w_concat[(size_t)(FF + k) * FF + fq * 4]);
                    float2 a = S.decay2[k];
                    FMA8(w, a, p0, p1);
                }
                float* dst = &S.scratch[SCR_E2 + (ksl * 16 + fq) * 8];
                *reinterpret_cast<float4*>(dst)     = p0;
                *reinterpret_cast<float4*>(dst + 4) = p1;
            }
            BARS(7, 256);

            // --- Q3: G = z_corr combine + beta + c (warps 8-11) ---
            if (tq < 128) {
                const int r = tq >> 6, f = tq & 63;
                const int fq = f >> 2, c = f & 3;
                float zc = S.bcorr[f];
#pragma unroll
                for (int ksl = 0; ksl < 8; ++ksl)
                    zc += S.scratch[SCR_D + (ksl * 16 + fq) * 8 + r * 4 + c];
                float bsum = bcc;
#pragma unroll
                for (int kq = 0; kq < 4; ++kq)
                    bsum += S.scratch[SCR_E + (kq * 16 + fq) * 8 + r * 4 + c];
#pragma unroll
                for (int ksl = 0; ksl < 8; ++ksl)
                    bsum += S.scratch[SCR_E2 + (ksl * 16 + fq) * 8 + r * 4 + c];
                float beta = sigmoidf_(bsum);
                float xr = xreg_s[f * 2 + r];
                float ct = beta * zc + (1.f - beta) * xr;
                float m = mm_s[f * 2 + r];
                float cv = m * xcur_s[f * 2 + r] + (1.f - m) * ct;
                cc_s[f * 2 + r] = cv;
                size_t ob = ((size_t)t * BB + (b0 + r)) * (5 * FF);
                out[ob + FF + f]     = zc;
                out[ob + 2 * FF + f] = cv;
            }
            BARS(8, 256);

            // --- Q4: H = c-half of w_update/w_reset/w_value_mask, accumulate into SCR_B ---
            if (tq < 192) {
                const int gm = tq >> 6;
                const int t6 = tq & 63;
                const int uq = t6 & 31, kh = t6 >> 5;
                float4 p0 = make_float4(0.f, 0.f, 0.f, 0.f);
                float4 p1 = make_float4(0.f, 0.f, 0.f, 0.f);
                if (gm == 0) {
#pragma unroll 8
                    for (int i = 0; i < 32; ++i) {
                        int k = kh * 32 + i;
                        float4 w = *reinterpret_cast<const float4*>(&S.w_upd[k * UU + uq * 4]);
                        float2 a = S.cc2[k];
                        FMA8(w, a, p0, p1);
                    }
                } else {
                    const float* W = (gm == 1) ? w_reset : w_value_mask;
#pragma unroll 8
                    for (int i = 0; i < 32; ++i) {
                        int k = kh * 32 + i;
                        float4 w = *reinterpret_cast<const float4*>(&W[(size_t)k * UU + uq * 4]);
                        float2 a = S.cc2[k];
                        FMA8(w, a, p0, p1);
                    }
                }
                float* dst = &S.scratch[SCR_B + ((gm * 2 + kh) * 32 + uq) * 8];
                float4 q0 = *reinterpret_cast<float4*>(dst);
                float4 q1 = *reinterpret_cast<float4*>(dst + 4);
                q0.x += p0.x; q0.y += p0.y; q0.z += p0.z; q0.w += p0.w;
                q1.x += p1.x; q1.y += p1.y; q1.z += p1.z; q1.w += p1.w;
                *reinterpret_cast<float4*>(dst)     = q0;
                *reinterpret_cast<float4*>(dst + 4) = q1;
            }
            BARA(6, 512);   // publish B+H to P
        }
        __syncthreads();
    }

    // ---- epilogue: final carries ----
    if (tid < 256) {
        const int r = tid >> 7, u = tid & 127;
        out[OFF_H + (size_t)(b0 + r) * UU + u] = h_s[u * 2 + r];
    }
    if (tid < 128) {
        const int r = tid >> 6, f = tid & 63;
        out[OFF_TS + (size_t)(b0 + r) * FF + f] = ts_s[f * 2 + r];
        out[OFF_DT + (size_t)(b0 + r) * FF + f] = dtv_s[f * 2 + r];
    }
}

extern "C" void kernel_launch(void* const* d_in, const int* in_sizes, int n_in,
                              void* d_out, int out_size) {
    const float* inputs        = (const float*)d_in[0];
    const float* h0            = (const float*)d_in[1];
    const float* ts0           = (const float*)d_in[2];
    const float* dt0           = (const float*)d_in[3];
    const float* w_regression  = (const float*)d_in[4];
    const float* b_regression  = (const float*)d_in[5];
    const float* w_controleur  = (const float*)d_in[6];
    const float* b_controleur  = (const float*)d_in[7];
    const float* w_delta       = (const float*)d_in[8];
    const float* b_delta       = (const float*)d_in[9];
    const float* w_value_mask  = (const float*)d_in[10];
    const float* b_value_mask  = (const float*)d_in[11];
    const float* w_corr        = (const float*)d_in[12];
    const float* b_corr        = (const float*)d_in[13];
    const float* w_concat      = (const float*)d_in[14];
    const float* b_concat      = (const float*)d_in[15];
    const float* u_update      = (const float*)d_in[16];
    const float* w_update      = (const float*)d_in[17];
    const float* b_update      = (const float*)d_in[18];
    const float* u_reset       = (const float*)d_in[19];
    const float* w_reset       = (const float*)d_in[20];
    const float* b_reset       = (const float*)d_in[21];
    float* out = (float*)d_out;

    cudaFuncSetAttribute(padd_gru_kernel,
                         cudaFuncAttributeMaxDynamicSharedMemorySize,
                         (int)sizeof(Smem));
    padd_gru_kernel<<<NCTA, NTHREADS, sizeof(Smem)>>>(
        inputs, h0, ts0, dt0,
        w_regression, b_regression, w_controleur, b_controleur,
        w_delta, b_delta, w_value_mask, b_value_mask,
        w_corr, b_corr, w_concat, b_concat,
        u_update, w_update, b_update,
        u_reset, w_reset, b_reset,
        out);
}